// round 14
// baseline (speedup 1.0000x reference)
#include <cuda_runtime.h>
#include <cuda_bf16.h>
#include <cstdint>

// Problem constants
#define BSESS 1024
#define NNODE 32
#define SLEN  50
#define HD    256
#define VOC   50000

// Scores GEMM config: C[1024,50000] split-bf16.
#define KC      64
#define NCHUNK  8
#define TILEB   16384              // 128 rows x 128 B
#define STAGE3  (3*TILEB)          // B + Ah + Al = 48 KB
#define SMEM_SZ (2*STAGE3)         // 96 KB double buffered

#define W3OFF   262144             // float offset of W3^T inside g_Wt
#define CONVC   296                // conv_split CTAs (2/SM, co-residable)

// Scratch
__device__ float g_sh[BSESS*HD];
__device__ float g_Wt[4*HD*HD + 2*HD*HD];   // 4 SAN mats + W3 (512x256)
__device__ __nv_bfloat16 g_Bh[(size_t)VOC*HD];
__device__ __nv_bfloat16 g_Bl[(size_t)VOC*HD];
__device__ __nv_bfloat16 g_Ah[BSESS*HD];
__device__ __nv_bfloat16 g_Al[BSESS*HD];

// ---------------------------------------------------------------------------
// Helpers (baseline ISA only)
// ---------------------------------------------------------------------------
__device__ __forceinline__ uint32_t smem_u32(const void* p) {
    uint32_t a;
    asm("{ .reg .u64 t; cvta.to.shared.u64 t, %1; cvt.u32.u64 %0, t; }"
        : "=r"(a) : "l"(p));
    return a;
}
__device__ __forceinline__ void cp16(uint32_t dst, const void* src) {
    asm volatile("cp.async.cg.shared.global [%0], [%1], 16;"
                 :: "r"(dst), "l"(src));
}
#define CP_COMMIT() asm volatile("cp.async.commit_group;" ::: "memory")
#define CP_WAIT(n)  asm volatile("cp.async.wait_group %0;" :: "n"(n) : "memory")

__device__ __forceinline__ uint32_t sw128(uint32_t x) {
    return x ^ ((x >> 3) & 0x70);
}
__device__ __forceinline__ void ldsm4(uint32_t* r, uint32_t addr) {
    asm volatile("ldmatrix.sync.aligned.m8n8.x4.shared.b16 {%0,%1,%2,%3}, [%4];"
                 : "=r"(r[0]), "=r"(r[1]), "=r"(r[2]), "=r"(r[3]) : "r"(addr));
}
__device__ __forceinline__ void mma16816(float* c, const uint32_t* a,
                                         const uint32_t* b) {
    asm volatile(
        "mma.sync.aligned.m16n8k16.row.col.f32.bf16.bf16.f32 "
        "{%0,%1,%2,%3}, {%4,%5,%6,%7}, {%8,%9}, {%0,%1,%2,%3};"
        : "+f"(c[0]), "+f"(c[1]), "+f"(c[2]), "+f"(c[3])
        : "r"(a[0]), "r"(a[1]), "r"(a[2]), "r"(a[3]), "r"(b[0]), "r"(b[1]));
}

// ---------------------------------------------------------------------------
// One-time weight transpose into packed [k][col] layout:
//   g_Wt[base + (k>>2)*1024 + col*4 + (k&3)] = W[col][k]
// ---------------------------------------------------------------------------
__global__ void transpose_w(const float* __restrict__ Wv,
                            const float* __restrict__ Wo,
                            const float* __restrict__ d1w,
                            const float* __restrict__ d2w,
                            const float* __restrict__ W3w) {
    int m = blockIdx.z;
    int kt = blockIdx.x*32, ct = blockIdx.y*32;
    const float* src; float* dst; int KD;
    if (m < 4) {
        if (kt >= 256) return;
        KD = 256; dst = g_Wt + m*65536;
        src = (m==0) ? Wv : (m==1) ? Wo : (m==2) ? d1w : d2w;
    } else {
        KD = 512; dst = g_Wt + W3OFF; src = W3w;
    }
    int x = threadIdx.x & 31, y8 = threadIdx.x >> 5;
    int k = kt + x;
    for (int i = y8; i < 32; i += 8) {
        int col = ct + i;
        dst[((k >> 2) << 10) + col*4 + (k & 3)] = src[(size_t)col*KD + k];
    }
}

// ---------------------------------------------------------------------------
// Fused chain kernel: vn gather -> 3x SAN blocks -> W3 -> s_h + A bf16 split.
// 512 threads/CTA (16 warps = 4/SMSP for latency hiding). Thread (col, rg)
// owns output column col for rows rg*4..rg*4+3. Weight reads from g_Wt are
// warp-coalesced and register double-buffered one 32-k chunk ahead. smem
// `in` reads are warp-uniform broadcasts.
// ---------------------------------------------------------------------------
__global__ void __launch_bounds__(512, 1)
chain_kernel(const float* __restrict__ node_emb,
             const float* __restrict__ itemset_len,
             const int*   __restrict__ sequence,
             const float* __restrict__ bv,  const float* __restrict__ bo,
             const float* __restrict__ d1b, const float* __restrict__ d2b,
             const float* __restrict__ W3b) {
    __shared__ float sv[8*HD];
    __shared__ float sx[8*HD];
    __shared__ float sa[8*HD];
    __shared__ float st[8*HD];
    int tid = threadIdx.x, w = tid >> 5, lane = tid & 31;
    int col = tid & 255, rg = tid >> 8;      // rg in {0,1}
    int b0 = blockIdx.x * 8;

    // ---- v_n gather: 16 warps; warp w -> row (w&7), half (w>>3) ----
    {
        int row = w & 7, half = w >> 3;
        int b = b0 + row;
        int t = b*SLEN + (SLEN-1);
        int s0 = sequence[t*3+0], s1 = sequence[t*3+1], s2 = sequence[t*3+2];
        float inv = 1.f / itemset_len[t];
        const float* base = node_emb + (size_t)b*NNODE*HD;
        int c = lane*8 + half*4;
        float4 acc = make_float4(0.f, 0.f, 0.f, 0.f);
        if (s0 != NNODE) { float4 v = *(const float4*)&base[s0*HD + c];
            acc.x+=v.x; acc.y+=v.y; acc.z+=v.z; acc.w+=v.w; }
        if (s1 != NNODE) { float4 v = *(const float4*)&base[s1*HD + c];
            acc.x+=v.x; acc.y+=v.y; acc.z+=v.z; acc.w+=v.w; }
        if (s2 != NNODE) { float4 v = *(const float4*)&base[s2*HD + c];
            acc.x+=v.x; acc.y+=v.y; acc.z+=v.z; acc.w+=v.w; }
        acc.x*=inv; acc.y*=inv; acc.z*=inv; acc.w*=inv;
        *(float4*)&sv[row*HD + c] = acc;
        *(float4*)&sx[row*HD + c] = acc;
    }
    __syncthreads();

    const float* btab[4] = {bv, bo, d1b, d2b};
    const float* intab[4]  = {sx, st, sa, st};
    float*       outtab[4] = {st, sa, st, sx};

    for (int j = 0; j <= 12; j++) {
        bool w3 = (j == 12);
        int sp = j & 3;
        const float* wt = w3 ? (g_Wt + W3OFF) : (g_Wt + sp*65536);
        int nc = w3 ? 16 : 8;
        const float* in_s = intab[sp];
        float* out_s = outtab[sp];

        float acc[4];
        #pragma unroll
        for (int r = 0; r < 4; r++) acc[r] = 0.f;

        float4 wc[8], wn[8];
        #pragma unroll
        for (int q = 0; q < 8; q++)
            wc[q] = *(const float4*)&wt[(size_t)q*1024 + col*4];

        for (int c = 0; c < nc; c++) {
            if (c + 1 < nc) {
                #pragma unroll
                for (int q = 0; q < 8; q++)
                    wn[q] = *(const float4*)&wt[(size_t)((c+1)*8 + q)*1024
                                                + col*4];
            }
            const float* in = w3 ? ((c < 8) ? sv : sx) : in_s;
            int l0 = (c & 7)*32;
            #pragma unroll
            for (int q = 0; q < 8; q++) {
                #pragma unroll
                for (int r = 0; r < 4; r++) {
                    float4 a = *(const float4*)&in[(rg*4 + r)*HD + l0 + q*4];
                    acc[r] += a.x*wc[q].x + a.y*wc[q].y
                            + a.z*wc[q].z + a.w*wc[q].w;
                }
            }
            if (c + 1 < nc) {
                #pragma unroll
                for (int q = 0; q < 8; q++) wc[q] = wn[q];
            }
        }

        if (!w3) {
            float bias = btab[sp][col];
            #pragma unroll
            for (int r = 0; r < 4; r++) {
                int row = rg*4 + r;
                float v = acc[r] + bias;
                if (sp == 2) v = fmaxf(v, 0.f);
                if (sp == 3) v += sa[row*HD + col];
                out_s[row*HD + col] = v;
            }
            __syncthreads();
        } else {
            float bias = W3b[col];
            #pragma unroll
            for (int r = 0; r < 4; r++) {
                int gr = b0 + rg*4 + r;
                float v = acc[r] + bias;
                g_sh[gr*HD + col] = v;
                __nv_bfloat16 h = __float2bfloat16(v);
                __nv_bfloat16 l = __float2bfloat16(v - __bfloat162float(h));
                g_Ah[gr*HD + col] = h;
                g_Al[gr*HD + col] = l;
            }
        }
    }
}

// ---------------------------------------------------------------------------
// fp32 -> (bf16 hi, bf16 lo) split (B side). Grid-stride, co-residable.
// ---------------------------------------------------------------------------
__global__ void __launch_bounds__(256)
conv_split(const float* __restrict__ src,
           __nv_bfloat16* __restrict__ hi,
           __nv_bfloat16* __restrict__ lo, int n4) {
    for (int i = blockIdx.x*256 + threadIdx.x; i < n4; i += CONVC*256) {
        float4 v = ((const float4*)src)[i];
        __nv_bfloat16 h0 = __float2bfloat16(v.x), h1 = __float2bfloat16(v.y),
                      h2 = __float2bfloat16(v.z), h3 = __float2bfloat16(v.w);
        __nv_bfloat16 l0 = __float2bfloat16(v.x - __bfloat162float(h0));
        __nv_bfloat16 l1 = __float2bfloat16(v.y - __bfloat162float(h1));
        __nv_bfloat16 l2 = __float2bfloat16(v.z - __bfloat162float(h2));
        __nv_bfloat16 l3 = __float2bfloat16(v.w - __bfloat162float(h3));
        ((__nv_bfloat162*)hi)[i*2+0] = __nv_bfloat162(h0, h1);
        ((__nv_bfloat162*)hi)[i*2+1] = __nv_bfloat162(h2, h3);
        ((__nv_bfloat162*)lo)[i*2+0] = __nv_bfloat162(l0, l1);
        ((__nv_bfloat162*)lo)[i*2+1] = __nv_bfloat162(l2, l3);
    }
}

// ---------------------------------------------------------------------------
// Scores GEMM (mma.sync bf16, split-fp32). grid (8 m-tiles, 391 n-tiles).
// ---------------------------------------------------------------------------
__global__ void __launch_bounds__(256, 2)
scores_kernel(float* __restrict__ out) {
    extern __shared__ char smem[];
    uint32_t sb = smem_u32(smem);
    int tid = threadIdx.x, lane = tid & 31, wid = tid >> 5;
    int wm = wid >> 2, wn = wid & 3;
    int m0 = blockIdx.x * 128, n0 = blockIdx.y * 128;
    int q = lane >> 3, r8 = lane & 7;

    uint32_t a_row = (uint32_t)(wm*64 + (q & 1)*8 + r8);
    uint32_t a_kb  = (uint32_t)((q >> 1) * 16);
    uint32_t b_row = (uint32_t)(wn*32 + (q >> 1)*8 + r8);
    uint32_t b_kb  = (uint32_t)((q & 1) * 16);

    float c[4][4][4];
    #pragma unroll
    for (int i = 0; i < 4; i++)
        #pragma unroll
        for (int j = 0; j < 4; j++)
            #pragma unroll
            for (int k = 0; k < 4; k++) c[i][j][k] = 0.f;

    auto load_stage = [&](int kc, int st) {
        bool hiterm = (kc < 4);
        const __nv_bfloat16* Bsrc = hiterm ? g_Bh : g_Bl;
        int k0 = (kc & 3) * KC;
        uint32_t base = sb + st*STAGE3;
        #pragma unroll
        for (int j = tid; j < 1024; j += 256) {
            int row = j >> 3, seg = j & 7;
            uint32_t off = sw128((uint32_t)(row*128 + seg*16));
            int gr = n0 + row; if (gr > VOC-1) gr = VOC-1;
            cp16(base + off, Bsrc + (size_t)gr*HD + k0 + seg*8);
            cp16(base + TILEB + off, g_Ah + (size_t)(m0 + row)*HD + k0 + seg*8);
            if (hiterm)
                cp16(base + 2*TILEB + off,
                     g_Al + (size_t)(m0 + row)*HD + k0 + seg*8);
        }
    };

    load_stage(0, 0);
    CP_COMMIT();

    for (int kc = 0; kc < NCHUNK; kc++) {
        int st = kc & 1;
        if (kc + 1 < NCHUNK) {
            load_stage(kc + 1, st ^ 1);
            CP_COMMIT();
            CP_WAIT(1);
        } else {
            CP_WAIT(0);
        }
        __syncthreads();
        uint32_t base = sb + st*STAGE3;
        bool hiterm = (kc < 4);
        #pragma unroll
        for (int ks = 0; ks < 4; ks++) {
            uint32_t b[4][2];
            #pragma unroll
            for (int nb = 0; nb < 2; nb++) {
                uint32_t r[4];
                ldsm4(r, base + sw128((b_row + nb*16)*128 + b_kb + ks*32));
                b[nb*2+0][0] = r[0]; b[nb*2+0][1] = r[1];
                b[nb*2+1][0] = r[2]; b[nb*2+1][1] = r[3];
            }
            #pragma unroll
            for (int mb = 0; mb < 4; mb++) {
                uint32_t asw = sw128((a_row + mb*16)*128 + a_kb + ks*32);
                uint32_t a[4];
                ldsm4(a, base + TILEB + asw);
                #pragma unroll
                for (int n8 = 0; n8 < 4; n8++)
                    mma16816(c[mb][n8], a, b[n8]);
                if (hiterm) {
                    uint32_t al[4];
                    ldsm4(al, base + 2*TILEB + asw);
                    #pragma unroll
                    for (int n8 = 0; n8 < 4; n8++)
                        mma16816(c[mb][n8], al, b[n8]);
                }
            }
        }
        __syncthreads();
    }

    #pragma unroll
    for (int mb = 0; mb < 4; mb++) {
        int gr0 = m0 + wm*64 + mb*16 + (lane >> 2);
        #pragma unroll
        for (int n8 = 0; n8 < 4; n8++) {
            int col = n0 + wn*32 + n8*8 + (lane & 3)*2;
            if (col < VOC) {
                *(float2*)&out[(size_t)gr0*VOC + col]     =
                    make_float2(c[mb][n8][0], c[mb][n8][1]);
                *(float2*)&out[(size_t)(gr0+8)*VOC + col] =
                    make_float2(c[mb][n8][2], c[mb][n8][3]);
            }
        }
    }
}

// ---------------------------------------------------------------------------
// y_hat[b] = dot(s_h[b], emb_weight[cue[b]])  (exact fp32 path)
// ---------------------------------------------------------------------------
__global__ void yhat_kernel(const float* __restrict__ emb,
                            const int*   __restrict__ cue,
                            float* __restrict__ out) {
    int b = blockIdx.x, tid = threadIdx.x;
    float v = g_sh[b*HD + tid] * emb[((size_t)cue[b])*HD + tid];
    #pragma unroll
    for (int o = 16; o > 0; o >>= 1) v += __shfl_down_sync(0xffffffffu, v, o);
    __shared__ float red[8];
    if ((tid & 31) == 0) red[tid >> 5] = v;
    __syncthreads();
    if (tid == 0) {
        float s = 0.f;
        #pragma unroll
        for (int i = 0; i < 8; i++) s += red[i];
        out[b] = s;
    }
}

// ---------------------------------------------------------------------------
static __nv_bfloat16 *pBh, *pBl;
static cudaStream_t sB = nullptr;
static cudaEvent_t evFork = nullptr, evConv = nullptr,
                   evChain = nullptr, evSide = nullptr;
static bool g_init = false;

static void resolve_once() {
    if (g_init) return;
    cudaGetSymbolAddress((void**)&pBh, g_Bh);
    cudaGetSymbolAddress((void**)&pBl, g_Bl);
    cudaFuncSetAttribute(scores_kernel,
                         cudaFuncAttributeMaxDynamicSharedMemorySize, SMEM_SZ);
    cudaStreamCreateWithFlags(&sB, cudaStreamNonBlocking);
    cudaEventCreateWithFlags(&evFork,  cudaEventDisableTiming);
    cudaEventCreateWithFlags(&evConv,  cudaEventDisableTiming);
    cudaEventCreateWithFlags(&evChain, cudaEventDisableTiming);
    cudaEventCreateWithFlags(&evSide,  cudaEventDisableTiming);
    g_init = true;
}

extern "C" void kernel_launch(void* const* d_in, const int* in_sizes, int n_in,
                              void* d_out, int out_size) {
    const float* node_embedding = (const float*)d_in[0];
    const float* emb_weight     = (const float*)d_in[1];
    const float* itemset_len    = (const float*)d_in[2];
    const float* in_proj_w      = (const float*)d_in[3];
    const float* in_proj_b      = (const float*)d_in[4];
    const float* out_proj_w     = (const float*)d_in[5];
    const float* out_proj_b     = (const float*)d_in[6];
    const float* d1_w           = (const float*)d_in[7];
    const float* d1_b           = (const float*)d_in[8];
    const float* d2_w           = (const float*)d_in[9];
    const float* d2_b           = (const float*)d_in[10];
    const float* W3_w           = (const float*)d_in[11];
    const float* W3_b           = (const float*)d_in[12];
    const int*   sequence       = (const int*)d_in[14];
    const int*   cue            = (const int*)d_in[16];

    resolve_once();
    float* out = (float*)d_out;

    // Fork: conv_split (co-residable) on side stream.
    cudaEventRecord(evFork, 0);
    cudaStreamWaitEvent(sB, evFork, 0);
    conv_split<<<CONVC, 256, 0, sB>>>(emb_weight, pBh, pBl, VOC*HD/4);
    cudaEventRecord(evConv, sB);

    // Main: weight transpose -> SAN chain (writes g_sh/g_Ah/g_Al).
    transpose_w<<<dim3(16, 8, 5), 256>>>(in_proj_w + 2*HD*HD, out_proj_w,
                                         d1_w, d2_w, W3_w);
    chain_kernel<<<BSESS/8, 512>>>(node_embedding, itemset_len, sequence,
                                   in_proj_b + 2*HD, out_proj_b,
                                   d1_b, d2_b, W3_b);
    cudaEventRecord(evChain, 0);

    // Side: yhat (needs chain) overlaps with scores.
    cudaStreamWaitEvent(sB, evChain, 0);
    yhat_kernel<<<BSESS, HD, 0, sB>>>(emb_weight, cue, out);
    cudaEventRecord(evSide, sB);

    // Main: scores (needs chain outputs + conv outputs).
    cudaStreamWaitEvent(0, evConv, 0);
    scores_kernel<<<dim3(8, (VOC + 127)/128), 256, SMEM_SZ>>>(out + BSESS);

    // Join side stream back into the capture-origin stream.
    cudaStreamWaitEvent(0, evSide, 0);
}

// round 15
// speedup vs baseline: 1.0076x; 1.0076x over previous
#include <cuda_runtime.h>
#include <cuda_bf16.h>
#include <cstdint>

// Problem constants
#define BSESS 1024
#define NNODE 32
#define SLEN  50
#define HD    256
#define VOC   50000

// Scores GEMM config: C[1024,50000] split-bf16.
#define KC      64
#define NCHUNK  8
#define TILEB   16384              // 128 rows x 128 B
#define STAGE3  (3*TILEB)          // B + Ah + Al = 48 KB
#define SMEM_SZ (2*STAGE3)         // 96 KB double buffered

#define W3OFF   262144             // float offset of W3^T inside g_Wt
#define CONVC   296                // conv_split CTAs (2/SM, co-residable)
#define CH_SMEM (32768 + 2*32768)  // chain: 32KB acts + 2x32KB W buffers

// Scratch
__device__ float g_sh[BSESS*HD];
__device__ float g_Wt[4*HD*HD + 2*HD*HD];   // 4 SAN mats + W3 (512x256)
__device__ __nv_bfloat16 g_Bh[(size_t)VOC*HD];
__device__ __nv_bfloat16 g_Bl[(size_t)VOC*HD];
__device__ __nv_bfloat16 g_Ah[BSESS*HD];
__device__ __nv_bfloat16 g_Al[BSESS*HD];

// ---------------------------------------------------------------------------
// Helpers (baseline ISA only)
// ---------------------------------------------------------------------------
__device__ __forceinline__ uint32_t smem_u32(const void* p) {
    uint32_t a;
    asm("{ .reg .u64 t; cvta.to.shared.u64 t, %1; cvt.u32.u64 %0, t; }"
        : "=r"(a) : "l"(p));
    return a;
}
__device__ __forceinline__ void cp16(uint32_t dst, const void* src) {
    asm volatile("cp.async.cg.shared.global [%0], [%1], 16;"
                 :: "r"(dst), "l"(src));
}
#define CP_COMMIT() asm volatile("cp.async.commit_group;" ::: "memory")
#define CP_WAIT(n)  asm volatile("cp.async.wait_group %0;" :: "n"(n) : "memory")

__device__ __forceinline__ uint32_t sw128(uint32_t x) {
    return x ^ ((x >> 3) & 0x70);
}
__device__ __forceinline__ void ldsm4(uint32_t* r, uint32_t addr) {
    asm volatile("ldmatrix.sync.aligned.m8n8.x4.shared.b16 {%0,%1,%2,%3}, [%4];"
                 : "=r"(r[0]), "=r"(r[1]), "=r"(r[2]), "=r"(r[3]) : "r"(addr));
}
__device__ __forceinline__ void mma16816(float* c, const uint32_t* a,
                                         const uint32_t* b) {
    asm volatile(
        "mma.sync.aligned.m16n8k16.row.col.f32.bf16.bf16.f32 "
        "{%0,%1,%2,%3}, {%4,%5,%6,%7}, {%8,%9}, {%0,%1,%2,%3};"
        : "+f"(c[0]), "+f"(c[1]), "+f"(c[2]), "+f"(c[3])
        : "r"(a[0]), "r"(a[1]), "r"(a[2]), "r"(a[3]), "r"(b[0]), "r"(b[1]));
}

// ---------------------------------------------------------------------------
// One-time weight transpose into packed [k][col] layout:
//   g_Wt[base + (k>>2)*1024 + col*4 + (k&3)] = W[col][k]
// Each 32-k chunk is a contiguous 32 KB block (8 q-rows x 1024 floats).
// ---------------------------------------------------------------------------
__global__ void transpose_w(const float* __restrict__ Wv,
                            const float* __restrict__ Wo,
                            const float* __restrict__ d1w,
                            const float* __restrict__ d2w,
                            const float* __restrict__ W3w) {
    int m = blockIdx.z;
    int kt = blockIdx.x*32, ct = blockIdx.y*32;
    const float* src; float* dst; int KD;
    if (m < 4) {
        if (kt >= 256) return;
        KD = 256; dst = g_Wt + m*65536;
        src = (m==0) ? Wv : (m==1) ? Wo : (m==2) ? d1w : d2w;
    } else {
        KD = 512; dst = g_Wt + W3OFF; src = W3w;
    }
    int x = threadIdx.x & 31, y8 = threadIdx.x >> 5;
    int k = kt + x;
    for (int i = y8; i < 32; i += 8) {
        int col = ct + i;
        dst[((k >> 2) << 10) + col*4 + (k & 3)] = src[(size_t)col*KD + k];
    }
}

// ---------------------------------------------------------------------------
// Fused chain kernel: vn gather -> 3x SAN blocks -> W3 -> s_h + A bf16 split.
// 128 CTAs x 8 rows, 256 threads. W chunks (32 KB each) stream into smem via
// cp.async double-buffering. Thread tid copies exactly the W floats it later
// reads ([q*1024 + tid*4]) so no barrier is needed for W — only per-step
// output barriers (13 total). Registers stay low; L2 latency hides in the
// async pipeline.
// ---------------------------------------------------------------------------
__global__ void __launch_bounds__(256, 1)
chain_kernel(const float* __restrict__ node_emb,
             const float* __restrict__ itemset_len,
             const int*   __restrict__ sequence,
             const float* __restrict__ bv,  const float* __restrict__ bo,
             const float* __restrict__ d1b, const float* __restrict__ d2b,
             const float* __restrict__ W3b) {
    extern __shared__ float cs[];
    float* sv = cs;            // 8 x 256
    float* sx = cs + 2048;
    float* sa = cs + 4096;
    float* st = cs + 6144;
    float* wb = cs + 8192;     // 2 x 8192 floats (W double buffer)
    uint32_t wb_u32 = smem_u32(wb);

    int tid = threadIdx.x, w = tid >> 5, lane = tid & 31;
    int b0 = blockIdx.x * 8;

    // ---- v_n gather: warp w -> row w ----
    {
        int b = b0 + w;
        int t = b*SLEN + (SLEN-1);
        int s0 = sequence[t*3+0], s1 = sequence[t*3+1], s2 = sequence[t*3+2];
        float inv = 1.f / itemset_len[t];
        const float* base = node_emb + (size_t)b*NNODE*HD;
        #pragma unroll
        for (int p = 0; p < 2; p++) {
            int c = lane*8 + p*4;
            float4 acc = make_float4(0.f, 0.f, 0.f, 0.f);
            if (s0 != NNODE) { float4 v = *(const float4*)&base[s0*HD + c];
                acc.x+=v.x; acc.y+=v.y; acc.z+=v.z; acc.w+=v.w; }
            if (s1 != NNODE) { float4 v = *(const float4*)&base[s1*HD + c];
                acc.x+=v.x; acc.y+=v.y; acc.z+=v.z; acc.w+=v.w; }
            if (s2 != NNODE) { float4 v = *(const float4*)&base[s2*HD + c];
                acc.x+=v.x; acc.y+=v.y; acc.z+=v.z; acc.w+=v.w; }
            acc.x*=inv; acc.y*=inv; acc.z*=inv; acc.w*=inv;
            *(float4*)&sv[w*HD + c] = acc;
            *(float4*)&sx[w*HD + c] = acc;
        }
    }
    __syncthreads();

    const float* btab[4] = {bv, bo, d1b, d2b};
    const float* intab[4]  = {sx, st, sa, st};
    float*       outtab[4] = {st, sa, st, sx};

    for (int j = 0; j <= 12; j++) {
        bool w3 = (j == 12);
        int sp = j & 3;
        const float* wt = w3 ? (g_Wt + W3OFF) : (g_Wt + sp*65536);
        int nc = w3 ? 16 : 8;
        const float* in_s = intab[sp];
        float* out_s = outtab[sp];

        float acc[8];
        #pragma unroll
        for (int r = 0; r < 8; r++) acc[r] = 0.f;

        // Prologue: async-load chunk 0 into buffer 0.
        #pragma unroll
        for (int q = 0; q < 8; q++)
            cp16(wb_u32 + (q*1024 + tid*4)*4, wt + q*1024 + tid*4);
        CP_COMMIT();

        int pb = 0;
        for (int c = 0; c < nc; c++) {
            if (c + 1 < nc) {
                uint32_t nb = wb_u32 + (pb ^ 1)*32768;
                const float* src = wt + (size_t)(c+1)*8192;
                #pragma unroll
                for (int q = 0; q < 8; q++)
                    cp16(nb + (q*1024 + tid*4)*4, src + q*1024 + tid*4);
                CP_COMMIT();
                CP_WAIT(1);
            } else {
                CP_WAIT(0);
            }
            const float* wsm = wb + pb*8192;
            const float* in = w3 ? ((c < 8) ? sv : sx) : in_s;
            int l0 = (c & 7)*32;
            #pragma unroll
            for (int q = 0; q < 8; q++) {
                float4 wq = *(const float4*)&wsm[q*1024 + tid*4];
                #pragma unroll
                for (int r = 0; r < 8; r++) {
                    float4 a = *(const float4*)&in[r*HD + l0 + q*4];
                    acc[r] += a.x*wq.x + a.y*wq.y + a.z*wq.z + a.w*wq.w;
                }
            }
            pb ^= 1;
        }

        if (!w3) {
            float bias = btab[sp][tid];
            #pragma unroll
            for (int r = 0; r < 8; r++) {
                float v = acc[r] + bias;
                if (sp == 2) v = fmaxf(v, 0.f);
                if (sp == 3) v += sa[r*HD + tid];
                out_s[r*HD + tid] = v;
            }
            __syncthreads();
        } else {
            float bias = W3b[tid];
            #pragma unroll
            for (int r = 0; r < 8; r++) {
                int gr = b0 + r;
                float v = acc[r] + bias;
                g_sh[gr*HD + tid] = v;
                __nv_bfloat16 h = __float2bfloat16(v);
                __nv_bfloat16 l = __float2bfloat16(v - __bfloat162float(h));
                g_Ah[gr*HD + tid] = h;
                g_Al[gr*HD + tid] = l;
            }
        }
    }
}

// ---------------------------------------------------------------------------
// fp32 -> (bf16 hi, bf16 lo) split (B side). Grid-stride, co-residable.
// ---------------------------------------------------------------------------
__global__ void __launch_bounds__(256)
conv_split(const float* __restrict__ src,
           __nv_bfloat16* __restrict__ hi,
           __nv_bfloat16* __restrict__ lo, int n4) {
    for (int i = blockIdx.x*256 + threadIdx.x; i < n4; i += CONVC*256) {
        float4 v = ((const float4*)src)[i];
        __nv_bfloat16 h0 = __float2bfloat16(v.x), h1 = __float2bfloat16(v.y),
                      h2 = __float2bfloat16(v.z), h3 = __float2bfloat16(v.w);
        __nv_bfloat16 l0 = __float2bfloat16(v.x - __bfloat162float(h0));
        __nv_bfloat16 l1 = __float2bfloat16(v.y - __bfloat162float(h1));
        __nv_bfloat16 l2 = __float2bfloat16(v.z - __bfloat162float(h2));
        __nv_bfloat16 l3 = __float2bfloat16(v.w - __bfloat162float(h3));
        ((__nv_bfloat162*)hi)[i*2+0] = __nv_bfloat162(h0, h1);
        ((__nv_bfloat162*)hi)[i*2+1] = __nv_bfloat162(h2, h3);
        ((__nv_bfloat162*)lo)[i*2+0] = __nv_bfloat162(l0, l1);
        ((__nv_bfloat162*)lo)[i*2+1] = __nv_bfloat162(l2, l3);
    }
}

// ---------------------------------------------------------------------------
// Scores GEMM (mma.sync bf16, split-fp32). grid (8 m-tiles, 391 n-tiles).
// ---------------------------------------------------------------------------
__global__ void __launch_bounds__(256, 2)
scores_kernel(float* __restrict__ out) {
    extern __shared__ char smem[];
    uint32_t sb = smem_u32(smem);
    int tid = threadIdx.x, lane = tid & 31, wid = tid >> 5;
    int wm = wid >> 2, wn = wid & 3;
    int m0 = blockIdx.x * 128, n0 = blockIdx.y * 128;
    int q = lane >> 3, r8 = lane & 7;

    uint32_t a_row = (uint32_t)(wm*64 + (q & 1)*8 + r8);
    uint32_t a_kb  = (uint32_t)((q >> 1) * 16);
    uint32_t b_row = (uint32_t)(wn*32 + (q >> 1)*8 + r8);
    uint32_t b_kb  = (uint32_t)((q & 1) * 16);

    float c[4][4][4];
    #pragma unroll
    for (int i = 0; i < 4; i++)
        #pragma unroll
        for (int j = 0; j < 4; j++)
            #pragma unroll
            for (int k = 0; k < 4; k++) c[i][j][k] = 0.f;

    auto load_stage = [&](int kc, int st) {
        bool hiterm = (kc < 4);
        const __nv_bfloat16* Bsrc = hiterm ? g_Bh : g_Bl;
        int k0 = (kc & 3) * KC;
        uint32_t base = sb + st*STAGE3;
        #pragma unroll
        for (int j = tid; j < 1024; j += 256) {
            int row = j >> 3, seg = j & 7;
            uint32_t off = sw128((uint32_t)(row*128 + seg*16));
            int gr = n0 + row; if (gr > VOC-1) gr = VOC-1;
            cp16(base + off, Bsrc + (size_t)gr*HD + k0 + seg*8);
            cp16(base + TILEB + off, g_Ah + (size_t)(m0 + row)*HD + k0 + seg*8);
            if (hiterm)
                cp16(base + 2*TILEB + off,
                     g_Al + (size_t)(m0 + row)*HD + k0 + seg*8);
        }
    };

    load_stage(0, 0);
    CP_COMMIT();

    for (int kc = 0; kc < NCHUNK; kc++) {
        int st = kc & 1;
        if (kc + 1 < NCHUNK) {
            load_stage(kc + 1, st ^ 1);
            CP_COMMIT();
            CP_WAIT(1);
        } else {
            CP_WAIT(0);
        }
        __syncthreads();
        uint32_t base = sb + st*STAGE3;
        bool hiterm = (kc < 4);
        #pragma unroll
        for (int ks = 0; ks < 4; ks++) {
            uint32_t b[4][2];
            #pragma unroll
            for (int nb = 0; nb < 2; nb++) {
                uint32_t r[4];
                ldsm4(r, base + sw128((b_row + nb*16)*128 + b_kb + ks*32));
                b[nb*2+0][0] = r[0]; b[nb*2+0][1] = r[1];
                b[nb*2+1][0] = r[2]; b[nb*2+1][1] = r[3];
            }
            #pragma unroll
            for (int mb = 0; mb < 4; mb++) {
                uint32_t asw = sw128((a_row + mb*16)*128 + a_kb + ks*32);
                uint32_t a[4];
                ldsm4(a, base + TILEB + asw);
                #pragma unroll
                for (int n8 = 0; n8 < 4; n8++)
                    mma16816(c[mb][n8], a, b[n8]);
                if (hiterm) {
                    uint32_t al[4];
                    ldsm4(al, base + 2*TILEB + asw);
                    #pragma unroll
                    for (int n8 = 0; n8 < 4; n8++)
                        mma16816(c[mb][n8], al, b[n8]);
                }
            }
        }
        __syncthreads();
    }

    #pragma unroll
    for (int mb = 0; mb < 4; mb++) {
        int gr0 = m0 + wm*64 + mb*16 + (lane >> 2);
        #pragma unroll
        for (int n8 = 0; n8 < 4; n8++) {
            int col = n0 + wn*32 + n8*8 + (lane & 3)*2;
            if (col < VOC) {
                *(float2*)&out[(size_t)gr0*VOC + col]     =
                    make_float2(c[mb][n8][0], c[mb][n8][1]);
                *(float2*)&out[(size_t)(gr0+8)*VOC + col] =
                    make_float2(c[mb][n8][2], c[mb][n8][3]);
            }
        }
    }
}

// ---------------------------------------------------------------------------
// y_hat[b] = dot(s_h[b], emb_weight[cue[b]])  (exact fp32 path)
// ---------------------------------------------------------------------------
__global__ void yhat_kernel(const float* __restrict__ emb,
                            const int*   __restrict__ cue,
                            float* __restrict__ out) {
    int b = blockIdx.x, tid = threadIdx.x;
    float v = g_sh[b*HD + tid] * emb[((size_t)cue[b])*HD + tid];
    #pragma unroll
    for (int o = 16; o > 0; o >>= 1) v += __shfl_down_sync(0xffffffffu, v, o);
    __shared__ float red[8];
    if ((tid & 31) == 0) red[tid >> 5] = v;
    __syncthreads();
    if (tid == 0) {
        float s = 0.f;
        #pragma unroll
        for (int i = 0; i < 8; i++) s += red[i];
        out[b] = s;
    }
}

// ---------------------------------------------------------------------------
static __nv_bfloat16 *pBh, *pBl;
static cudaStream_t sB = nullptr;
static cudaEvent_t evFork = nullptr, evConv = nullptr,
                   evChain = nullptr, evSide = nullptr;
static bool g_init = false;

static void resolve_once() {
    if (g_init) return;
    cudaGetSymbolAddress((void**)&pBh, g_Bh);
    cudaGetSymbolAddress((void**)&pBl, g_Bl);
    cudaFuncSetAttribute(scores_kernel,
                         cudaFuncAttributeMaxDynamicSharedMemorySize, SMEM_SZ);
    cudaFuncSetAttribute(chain_kernel,
                         cudaFuncAttributeMaxDynamicSharedMemorySize, CH_SMEM);
    cudaStreamCreateWithFlags(&sB, cudaStreamNonBlocking);
    cudaEventCreateWithFlags(&evFork,  cudaEventDisableTiming);
    cudaEventCreateWithFlags(&evConv,  cudaEventDisableTiming);
    cudaEventCreateWithFlags(&evChain, cudaEventDisableTiming);
    cudaEventCreateWithFlags(&evSide,  cudaEventDisableTiming);
    g_init = true;
}

extern "C" void kernel_launch(void* const* d_in, const int* in_sizes, int n_in,
                              void* d_out, int out_size) {
    const float* node_embedding = (const float*)d_in[0];
    const float* emb_weight     = (const float*)d_in[1];
    const float* itemset_len    = (const float*)d_in[2];
    const float* in_proj_w      = (const float*)d_in[3];
    const float* in_proj_b      = (const float*)d_in[4];
    const float* out_proj_w     = (const float*)d_in[5];
    const float* out_proj_b     = (const float*)d_in[6];
    const float* d1_w           = (const float*)d_in[7];
    const float* d1_b           = (const float*)d_in[8];
    const float* d2_w           = (const float*)d_in[9];
    const float* d2_b           = (const float*)d_in[10];
    const float* W3_w           = (const float*)d_in[11];
    const float* W3_b           = (const float*)d_in[12];
    const int*   sequence       = (const int*)d_in[14];
    const int*   cue            = (const int*)d_in[16];

    resolve_once();
    float* out = (float*)d_out;

    // Fork: conv_split (co-residable) on side stream.
    cudaEventRecord(evFork, 0);
    cudaStreamWaitEvent(sB, evFork, 0);
    conv_split<<<CONVC, 256, 0, sB>>>(emb_weight, pBh, pBl, VOC*HD/4);
    cudaEventRecord(evConv, sB);

    // Main: weight transpose -> SAN chain (writes g_sh/g_Ah/g_Al).
    transpose_w<<<dim3(16, 8, 5), 256>>>(in_proj_w + 2*HD*HD, out_proj_w,
                                         d1_w, d2_w, W3_w);
    chain_kernel<<<BSESS/8, 256, CH_SMEM>>>(node_embedding, itemset_len,
                                            sequence,
                                            in_proj_b + 2*HD, out_proj_b,
                                            d1_b, d2_b, W3_b);
    cudaEventRecord(evChain, 0);

    // Side: yhat (needs chain) overlaps with scores.
    cudaStreamWaitEvent(sB, evChain, 0);
    yhat_kernel<<<BSESS, HD, 0, sB>>>(emb_weight, cue, out);
    cudaEventRecord(evSide, sB);

    // Main: scores (needs chain outputs + conv outputs).
    cudaStreamWaitEvent(0, evConv, 0);
    scores_kernel<<<dim3(8, (VOC + 127)/128), 256, SMEM_SZ>>>(out + BSESS);

    // Join side stream back into the capture-origin stream.
    cudaStreamWaitEvent(0, evSide, 0);
}

// round 16
// speedup vs baseline: 1.2075x; 1.1984x over previous
#include <cuda_runtime.h>
#include <cuda_bf16.h>
#include <cstdint>

// Problem constants
#define BSESS 1024
#define NNODE 32
#define SLEN  50
#define HD    256
#define VOC   50000

// Scores GEMM config: C[1024,50000] split-bf16.
#define KC      64
#define NCHUNK  8
#define TILEB   16384              // 128 rows x 128 B
#define STAGE3  (3*TILEB)          // B + Ah + Al = 48 KB
#define SMEM_SZ (2*STAGE3)         // 96 KB double buffered

#define CONVC   296                // conv_split CTAs (2/SM, co-residable)

// Chain-MMA config: 64 CTAs x 16 rows, tensor-core SAN chain.
#define W3OFFB  262144             // bf16-element offset of W3 in g_Wh/g_Wl
// smem: sv/sx/sa/st fp32 16x256 (4x16KB) | ah,al bf16 8 chunk-tiles (2x16KB) |
//       W double buffer (2x32KB)
#define CH_SV   0
#define CH_SX   16384
#define CH_SA   32768
#define CH_ST   49152
#define CH_AH   65536
#define CH_AL   81920
#define CH_WB   98304
#define CH2_SMEM (98304 + 2*32768)   // 163840

// Scratch
__device__ float g_sh[BSESS*HD];
__device__ __nv_bfloat16 g_Wh[4*HD*HD + 2*HD*HD];
__device__ __nv_bfloat16 g_Wl[4*HD*HD + 2*HD*HD];
__device__ __nv_bfloat16 g_Bh[(size_t)VOC*HD];
__device__ __nv_bfloat16 g_Bl[(size_t)VOC*HD];
__device__ __nv_bfloat16 g_Ah[BSESS*HD];
__device__ __nv_bfloat16 g_Al[BSESS*HD];

// ---------------------------------------------------------------------------
// Helpers (baseline ISA only)
// ---------------------------------------------------------------------------
__device__ __forceinline__ uint32_t smem_u32(const void* p) {
    uint32_t a;
    asm("{ .reg .u64 t; cvta.to.shared.u64 t, %1; cvt.u32.u64 %0, t; }"
        : "=r"(a) : "l"(p));
    return a;
}
__device__ __forceinline__ void cp16(uint32_t dst, const void* src) {
    asm volatile("cp.async.cg.shared.global [%0], [%1], 16;"
                 :: "r"(dst), "l"(src));
}
#define CP_COMMIT() asm volatile("cp.async.commit_group;" ::: "memory")
#define CP_WAIT(n)  asm volatile("cp.async.wait_group %0;" :: "n"(n) : "memory")

__device__ __forceinline__ uint32_t sw128(uint32_t x) {
    return x ^ ((x >> 3) & 0x70);
}
__device__ __forceinline__ void ldsm4(uint32_t* r, uint32_t addr) {
    asm volatile("ldmatrix.sync.aligned.m8n8.x4.shared.b16 {%0,%1,%2,%3}, [%4];"
                 : "=r"(r[0]), "=r"(r[1]), "=r"(r[2]), "=r"(r[3]) : "r"(addr));
}
__device__ __forceinline__ void mma16816(float* c, const uint32_t* a,
                                         const uint32_t* b) {
    asm volatile(
        "mma.sync.aligned.m16n8k16.row.col.f32.bf16.bf16.f32 "
        "{%0,%1,%2,%3}, {%4,%5,%6,%7}, {%8,%9}, {%0,%1,%2,%3};"
        : "+f"(c[0]), "+f"(c[1]), "+f"(c[2]), "+f"(c[3])
        : "r"(a[0]), "r"(a[1]), "r"(a[2]), "r"(a[3]), "r"(b[0]), "r"(b[1]));
}

// ---------------------------------------------------------------------------
// One-time weight hi/lo split. W layout [out_col][k] (k contiguous) is ALREADY
// the mma B-operand layout; no transpose needed.
// ---------------------------------------------------------------------------
__global__ void wsplit(const float* __restrict__ Wv,
                       const float* __restrict__ Wo,
                       const float* __restrict__ d1w,
                       const float* __restrict__ d2w,
                       const float* __restrict__ W3w) {
    int m = blockIdx.z;
    const float* src; int n4; size_t off;
    if (m < 4) {
        src = (m==0)?Wv:(m==1)?Wo:(m==2)?d1w:d2w;
        n4 = 16384; off = (size_t)m*65536;
    } else {
        src = W3w; n4 = 32768; off = W3OFFB;
    }
    int i = blockIdx.x*256 + threadIdx.x;
    if (i >= n4) return;
    float4 v = ((const float4*)src)[i];
    __nv_bfloat16 h0 = __float2bfloat16(v.x), h1 = __float2bfloat16(v.y),
                  h2 = __float2bfloat16(v.z), h3 = __float2bfloat16(v.w);
    __nv_bfloat16 l0 = __float2bfloat16(v.x - __bfloat162float(h0));
    __nv_bfloat16 l1 = __float2bfloat16(v.y - __bfloat162float(h1));
    __nv_bfloat16 l2 = __float2bfloat16(v.z - __bfloat162float(h2));
    __nv_bfloat16 l3 = __float2bfloat16(v.w - __bfloat162float(h3));
    ((__nv_bfloat162*)(g_Wh+off))[i*2+0] = __nv_bfloat162(h0, h1);
    ((__nv_bfloat162*)(g_Wh+off))[i*2+1] = __nv_bfloat162(h2, h3);
    ((__nv_bfloat162*)(g_Wl+off))[i*2+0] = __nv_bfloat162(l0, l1);
    ((__nv_bfloat162*)(g_Wl+off))[i*2+1] = __nv_bfloat162(l2, l3);
}

// ---------------------------------------------------------------------------
// Tensor-core chain: vn gather -> 13 split-bf16 mma GEMM steps -> s_h + split.
// 64 CTAs x 16 rows (M=16 native), 256 threads (8 warps; warp w owns n-cols
// w*32..w*32+31). Per step: split activations to bf16 hi/lo smem tiles, then
// stream W hi/lo chunks ([256n x 64k] SW128, cp.async double-buffered) with
// 3-term accumulation (Ah.Wh + Al.Wh + Ah.Wl) — exact same ldsm/mma/swizzle
// patterns as scores_kernel.
// ---------------------------------------------------------------------------
__global__ void __launch_bounds__(256, 1)
chain_mma(const float* __restrict__ node_emb,
          const float* __restrict__ itemset_len,
          const int*   __restrict__ sequence,
          const float* __restrict__ bv,  const float* __restrict__ bo,
          const float* __restrict__ d1b, const float* __restrict__ d2b,
          const float* __restrict__ W3b) {
    extern __shared__ char cs8[];
    float* sv = (float*)(cs8 + CH_SV);
    float* sx = (float*)(cs8 + CH_SX);
    float* sa = (float*)(cs8 + CH_SA);
    float* st = (float*)(cs8 + CH_ST);
    char*  ah = cs8 + CH_AH;
    char*  al = cs8 + CH_AL;
    uint32_t ah_u = smem_u32(ah), al_u = smem_u32(al);
    uint32_t wb_u = smem_u32(cs8 + CH_WB);

    int tid = threadIdx.x, w = tid >> 5, lane = tid & 31;
    int q = lane >> 3, r8 = lane & 7;
    int b0row = blockIdx.x * 16;

    // ---- v_n gather: warp w -> rows {2w, 2w+1} ----
    #pragma unroll
    for (int rr = 0; rr < 2; rr++) {
        int row = w*2 + rr;
        int b = b0row + row;
        int t = b*SLEN + (SLEN-1);
        int s0 = sequence[t*3+0], s1 = sequence[t*3+1], s2 = sequence[t*3+2];
        float inv = 1.f / itemset_len[t];
        const float* base = node_emb + (size_t)b*NNODE*HD;
        #pragma unroll
        for (int p = 0; p < 2; p++) {
            int c = lane*8 + p*4;
            float4 acc = make_float4(0.f, 0.f, 0.f, 0.f);
            if (s0 != NNODE) { float4 v = *(const float4*)&base[s0*HD + c];
                acc.x+=v.x; acc.y+=v.y; acc.z+=v.z; acc.w+=v.w; }
            if (s1 != NNODE) { float4 v = *(const float4*)&base[s1*HD + c];
                acc.x+=v.x; acc.y+=v.y; acc.z+=v.z; acc.w+=v.w; }
            if (s2 != NNODE) { float4 v = *(const float4*)&base[s2*HD + c];
                acc.x+=v.x; acc.y+=v.y; acc.z+=v.z; acc.w+=v.w; }
            acc.x*=inv; acc.y*=inv; acc.z*=inv; acc.w*=inv;
            *(float4*)&sv[row*HD + c] = acc;
            *(float4*)&sx[row*HD + c] = acc;
        }
    }
    __syncthreads();

    // Fragment coordinates (identical scheme to scores_kernel)
    uint32_t a_row = (uint32_t)((q & 1)*8 + r8);
    uint32_t a_kb  = (uint32_t)((q >> 1) * 16);
    uint32_t b_row = (uint32_t)(w*32 + (q >> 1)*8 + r8);
    uint32_t b_kb  = (uint32_t)((q & 1) * 16);
    int er = lane >> 2, ec = (lane & 3)*2;

    const float* btab[4] = {bv, bo, d1b, d2b};
    const float* intab[4]  = {sx, st, sa, st};
    float*       outtab[4] = {st, sa, st, sx};

    // A-convert helper indices
    int crow = tid >> 4, ckb = (tid & 15) * 16;

    for (int j = 0; j <= 12; j++) {
        bool w3 = (j == 12);
        int sp = j & 3;
        const __nv_bfloat16* Wh = g_Wh + (w3 ? W3OFFB : sp*65536);
        const __nv_bfloat16* Wl = g_Wl + (w3 ? W3OFFB : sp*65536);
        int K = w3 ? 512 : 256;
        int nkc = K / 64;            // 4 or 8 k-chunks per term
        int nch2 = 2 * nkc;          // total chunk passes (Wh + Wl)
        const float* in_s = intab[sp];
        float* out_s = outtab[sp];

        // ---- convert activations -> bf16 hi/lo chunk tiles ----
        #pragma unroll
        for (int half = 0; half < 2; half++) {
            if (half == 1 && !w3) break;
            const float* s0 = w3 ? (half ? sx : sv) : in_s;
            int cofs = half * 4;
            #pragma unroll
            for (int g = 0; g < 2; g++) {
                int kk = ckb + g*8;
                float4 f0 = *(const float4*)&s0[crow*HD + kk];
                float4 f1 = *(const float4*)&s0[crow*HD + kk + 4];
                float vals[8] = {f0.x,f0.y,f0.z,f0.w,f1.x,f1.y,f1.z,f1.w};
                uint4 hv, lv;
                __nv_bfloat162* hp = (__nv_bfloat162*)&hv;
                __nv_bfloat162* lp = (__nv_bfloat162*)&lv;
                #pragma unroll
                for (int e = 0; e < 4; e++) {
                    float ax = vals[2*e], ay = vals[2*e+1];
                    __nv_bfloat16 hx = __float2bfloat16(ax);
                    __nv_bfloat16 hy = __float2bfloat16(ay);
                    hp[e] = __nv_bfloat162(hx, hy);
                    lp[e] = __nv_bfloat162(
                        __float2bfloat16(ax - __bfloat162float(hx)),
                        __float2bfloat16(ay - __bfloat162float(hy)));
                }
                int chunk = cofs + (kk >> 6);
                uint32_t off = sw128((uint32_t)(crow*128 + (kk & 63)*2));
                *(uint4*)(ah + chunk*2048 + off) = hv;
                *(uint4*)(al + chunk*2048 + off) = lv;
            }
        }
        __syncthreads();

        float c[4][4];
        #pragma unroll
        for (int i = 0; i < 4; i++)
            #pragma unroll
            for (int k = 0; k < 4; k++) c[i][k] = 0.f;

        // ---- W chunk streaming + mma ----
        auto wload = [&](int kc, int stg) {
            const __nv_bfloat16* Wsrc = (kc < nkc) ? Wh : Wl;
            int k0 = (kc & (nkc-1)) * 64;
            uint32_t base = wb_u + stg*32768;
            #pragma unroll
            for (int jj = tid; jj < 2048; jj += 256) {
                int n = jj >> 3, seg = jj & 7;
                cp16(base + sw128((uint32_t)(n*128 + seg*16)),
                     Wsrc + (size_t)n*K + k0 + seg*8);
            }
        };
        wload(0, 0);
        CP_COMMIT();

        for (int kc = 0; kc < nch2; kc++) {
            int stg = kc & 1;
            if (kc + 1 < nch2) {
                wload(kc + 1, stg ^ 1);
                CP_COMMIT();
                CP_WAIT(1);
            } else {
                CP_WAIT(0);
            }
            __syncthreads();
            uint32_t base = wb_u + stg*32768;
            bool hiterm = (kc < nkc);
            int ca = kc & (nkc-1);
            uint32_t ab  = ah_u + ca*2048;
            uint32_t alb = al_u + ca*2048;
            #pragma unroll
            for (int ks = 0; ks < 4; ks++) {
                uint32_t b[4][2];
                #pragma unroll
                for (int nb = 0; nb < 2; nb++) {
                    uint32_t r[4];
                    ldsm4(r, base + sw128((b_row + nb*16)*128 + b_kb + ks*32));
                    b[nb*2+0][0] = r[0]; b[nb*2+0][1] = r[1];
                    b[nb*2+1][0] = r[2]; b[nb*2+1][1] = r[3];
                }
                uint32_t aswo = sw128(a_row*128 + a_kb + ks*32);
                uint32_t a[4];
                ldsm4(a, ab + aswo);
                #pragma unroll
                for (int n8 = 0; n8 < 4; n8++)
                    mma16816(c[n8], a, b[n8]);
                if (hiterm) {
                    uint32_t a2[4];
                    ldsm4(a2, alb + aswo);
                    #pragma unroll
                    for (int n8 = 0; n8 < 4; n8++)
                        mma16816(c[n8], a2, b[n8]);
                }
            }
            __syncthreads();
        }

        // ---- epilogue ----
        if (!w3) {
            const float* bias = btab[sp];
            #pragma unroll
            for (int n8 = 0; n8 < 4; n8++) {
                int cb = w*32 + n8*8 + ec;
                float b0v = bias[cb], b1v = bias[cb+1];
                float v00 = c[n8][0] + b0v, v01 = c[n8][1] + b1v;
                float v10 = c[n8][2] + b0v, v11 = c[n8][3] + b1v;
                if (sp == 2) {
                    v00 = fmaxf(v00, 0.f); v01 = fmaxf(v01, 0.f);
                    v10 = fmaxf(v10, 0.f); v11 = fmaxf(v11, 0.f);
                }
                if (sp == 3) {
                    v00 += sa[er*HD + cb];     v01 += sa[er*HD + cb + 1];
                    v10 += sa[(er+8)*HD + cb]; v11 += sa[(er+8)*HD + cb + 1];
                }
                out_s[er*HD + cb]       = v00;
                out_s[er*HD + cb + 1]   = v01;
                out_s[(er+8)*HD + cb]   = v10;
                out_s[(er+8)*HD + cb+1] = v11;
            }
            __syncthreads();
        } else {
            #pragma unroll
            for (int n8 = 0; n8 < 4; n8++) {
                int cb = w*32 + n8*8 + ec;
                float b0v = W3b[cb], b1v = W3b[cb+1];
                float vr[2][2] = {{c[n8][0] + b0v, c[n8][1] + b1v},
                                  {c[n8][2] + b0v, c[n8][3] + b1v}};
                #pragma unroll
                for (int rr = 0; rr < 2; rr++) {
                    int gr = b0row + er + rr*8;
                    #pragma unroll
                    for (int cc = 0; cc < 2; cc++) {
                        float v = vr[rr][cc];
                        g_sh[gr*HD + cb + cc] = v;
                        __nv_bfloat16 h = __float2bfloat16(v);
                        g_Ah[gr*HD + cb + cc] = h;
                        g_Al[gr*HD + cb + cc] =
                            __float2bfloat16(v - __bfloat162float(h));
                    }
                }
            }
        }
    }
}

// ---------------------------------------------------------------------------
// fp32 -> (bf16 hi, bf16 lo) split (B side). Grid-stride, co-residable.
// ---------------------------------------------------------------------------
__global__ void __launch_bounds__(256)
conv_split(const float* __restrict__ src,
           __nv_bfloat16* __restrict__ hi,
           __nv_bfloat16* __restrict__ lo, int n4) {
    for (int i = blockIdx.x*256 + threadIdx.x; i < n4; i += CONVC*256) {
        float4 v = ((const float4*)src)[i];
        __nv_bfloat16 h0 = __float2bfloat16(v.x), h1 = __float2bfloat16(v.y),
                      h2 = __float2bfloat16(v.z), h3 = __float2bfloat16(v.w);
        __nv_bfloat16 l0 = __float2bfloat16(v.x - __bfloat162float(h0));
        __nv_bfloat16 l1 = __float2bfloat16(v.y - __bfloat162float(h1));
        __nv_bfloat16 l2 = __float2bfloat16(v.z - __bfloat162float(h2));
        __nv_bfloat16 l3 = __float2bfloat16(v.w - __bfloat162float(h3));
        ((__nv_bfloat162*)hi)[i*2+0] = __nv_bfloat162(h0, h1);
        ((__nv_bfloat162*)hi)[i*2+1] = __nv_bfloat162(h2, h3);
        ((__nv_bfloat162*)lo)[i*2+0] = __nv_bfloat162(l0, l1);
        ((__nv_bfloat162*)lo)[i*2+1] = __nv_bfloat162(l2, l3);
    }
}

// ---------------------------------------------------------------------------
// Scores GEMM (mma.sync bf16, split-fp32). grid (8 m-tiles, 391 n-tiles).
// ---------------------------------------------------------------------------
__global__ void __launch_bounds__(256, 2)
scores_kernel(float* __restrict__ out) {
    extern __shared__ char smem[];
    uint32_t sb = smem_u32(smem);
    int tid = threadIdx.x, lane = tid & 31, wid = tid >> 5;
    int wm = wid >> 2, wn = wid & 3;
    int m0 = blockIdx.x * 128, n0 = blockIdx.y * 128;
    int q = lane >> 3, r8 = lane & 7;

    uint32_t a_row = (uint32_t)(wm*64 + (q & 1)*8 + r8);
    uint32_t a_kb  = (uint32_t)((q >> 1) * 16);
    uint32_t b_row = (uint32_t)(wn*32 + (q >> 1)*8 + r8);
    uint32_t b_kb  = (uint32_t)((q & 1) * 16);

    float c[4][4][4];
    #pragma unroll
    for (int i = 0; i < 4; i++)
        #pragma unroll
        for (int j = 0; j < 4; j++)
            #pragma unroll
            for (int k = 0; k < 4; k++) c[i][j][k] = 0.f;

    auto load_stage = [&](int kc, int st) {
        bool hiterm = (kc < 4);
        const __nv_bfloat16* Bsrc = hiterm ? g_Bh : g_Bl;
        int k0 = (kc & 3) * KC;
        uint32_t base = sb + st*STAGE3;
        #pragma unroll
        for (int j = tid; j < 1024; j += 256) {
            int row = j >> 3, seg = j & 7;
            uint32_t off = sw128((uint32_t)(row*128 + seg*16));
            int gr = n0 + row; if (gr > VOC-1) gr = VOC-1;
            cp16(base + off, Bsrc + (size_t)gr*HD + k0 + seg*8);
            cp16(base + TILEB + off, g_Ah + (size_t)(m0 + row)*HD + k0 + seg*8);
            if (hiterm)
                cp16(base + 2*TILEB + off,
                     g_Al + (size_t)(m0 + row)*HD + k0 + seg*8);
        }
    };

    load_stage(0, 0);
    CP_COMMIT();

    for (int kc = 0; kc < NCHUNK; kc++) {
        int st = kc & 1;
        if (kc + 1 < NCHUNK) {
            load_stage(kc + 1, st ^ 1);
            CP_COMMIT();
            CP_WAIT(1);
        } else {
            CP_WAIT(0);
        }
        __syncthreads();
        uint32_t base = sb + st*STAGE3;
        bool hiterm = (kc < 4);
        #pragma unroll
        for (int ks = 0; ks < 4; ks++) {
            uint32_t b[4][2];
            #pragma unroll
            for (int nb = 0; nb < 2; nb++) {
                uint32_t r[4];
                ldsm4(r, base + sw128((b_row + nb*16)*128 + b_kb + ks*32));
                b[nb*2+0][0] = r[0]; b[nb*2+0][1] = r[1];
                b[nb*2+1][0] = r[2]; b[nb*2+1][1] = r[3];
            }
            #pragma unroll
            for (int mb = 0; mb < 4; mb++) {
                uint32_t asw = sw128((a_row + mb*16)*128 + a_kb + ks*32);
                uint32_t a[4];
                ldsm4(a, base + TILEB + asw);
                #pragma unroll
                for (int n8 = 0; n8 < 4; n8++)
                    mma16816(c[mb][n8], a, b[n8]);
                if (hiterm) {
                    uint32_t al2[4];
                    ldsm4(al2, base + 2*TILEB + asw);
                    #pragma unroll
                    for (int n8 = 0; n8 < 4; n8++)
                        mma16816(c[mb][n8], al2, b[n8]);
                }
            }
        }
        __syncthreads();
    }

    #pragma unroll
    for (int mb = 0; mb < 4; mb++) {
        int gr0 = m0 + wm*64 + mb*16 + (lane >> 2);
        #pragma unroll
        for (int n8 = 0; n8 < 4; n8++) {
            int col = n0 + wn*32 + n8*8 + (lane & 3)*2;
            if (col < VOC) {
                *(float2*)&out[(size_t)gr0*VOC + col]     =
                    make_float2(c[mb][n8][0], c[mb][n8][1]);
                *(float2*)&out[(size_t)(gr0+8)*VOC + col] =
                    make_float2(c[mb][n8][2], c[mb][n8][3]);
            }
        }
    }
}

// ---------------------------------------------------------------------------
// y_hat[b] = dot(s_h[b], emb_weight[cue[b]])  (exact fp32 path)
// ---------------------------------------------------------------------------
__global__ void yhat_kernel(const float* __restrict__ emb,
                            const int*   __restrict__ cue,
                            float* __restrict__ out) {
    int b = blockIdx.x, tid = threadIdx.x;
    float v = g_sh[b*HD + tid] * emb[((size_t)cue[b])*HD + tid];
    #pragma unroll
    for (int o = 16; o > 0; o >>= 1) v += __shfl_down_sync(0xffffffffu, v, o);
    __shared__ float red[8];
    if ((tid & 31) == 0) red[tid >> 5] = v;
    __syncthreads();
    if (tid == 0) {
        float s = 0.f;
        #pragma unroll
        for (int i = 0; i < 8; i++) s += red[i];
        out[b] = s;
    }
}

// ---------------------------------------------------------------------------
static __nv_bfloat16 *pBh, *pBl;
static cudaStream_t sB = nullptr;
static cudaEvent_t evFork = nullptr, evConv = nullptr,
                   evChain = nullptr, evSide = nullptr;
static bool g_init = false;

static void resolve_once() {
    if (g_init) return;
    cudaGetSymbolAddress((void**)&pBh, g_Bh);
    cudaGetSymbolAddress((void**)&pBl, g_Bl);
    cudaFuncSetAttribute(scores_kernel,
                         cudaFuncAttributeMaxDynamicSharedMemorySize, SMEM_SZ);
    cudaFuncSetAttribute(chain_mma,
                         cudaFuncAttributeMaxDynamicSharedMemorySize, CH2_SMEM);
    cudaStreamCreateWithFlags(&sB, cudaStreamNonBlocking);
    cudaEventCreateWithFlags(&evFork,  cudaEventDisableTiming);
    cudaEventCreateWithFlags(&evConv,  cudaEventDisableTiming);
    cudaEventCreateWithFlags(&evChain, cudaEventDisableTiming);
    cudaEventCreateWithFlags(&evSide,  cudaEventDisableTiming);
    g_init = true;
}

extern "C" void kernel_launch(void* const* d_in, const int* in_sizes, int n_in,
                              void* d_out, int out_size) {
    const float* node_embedding = (const float*)d_in[0];
    const float* emb_weight     = (const float*)d_in[1];
    const float* itemset_len    = (const float*)d_in[2];
    const float* in_proj_w      = (const float*)d_in[3];
    const float* in_proj_b      = (const float*)d_in[4];
    const float* out_proj_w     = (const float*)d_in[5];
    const float* out_proj_b     = (const float*)d_in[6];
    const float* d1_w           = (const float*)d_in[7];
    const float* d1_b           = (const float*)d_in[8];
    const float* d2_w           = (const float*)d_in[9];
    const float* d2_b           = (const float*)d_in[10];
    const float* W3_w           = (const float*)d_in[11];
    const float* W3_b           = (const float*)d_in[12];
    const int*   sequence       = (const int*)d_in[14];
    const int*   cue            = (const int*)d_in[16];

    resolve_once();
    float* out = (float*)d_out;

    // Fork: conv_split (co-residable) on side stream.
    cudaEventRecord(evFork, 0);
    cudaStreamWaitEvent(sB, evFork, 0);
    conv_split<<<CONVC, 256, 0, sB>>>(emb_weight, pBh, pBl, VOC*HD/4);
    cudaEventRecord(evConv, sB);

    // Main: weight hi/lo split -> tensor-core SAN chain.
    wsplit<<<dim3(128, 1, 5), 256>>>(in_proj_w + 2*HD*HD, out_proj_w,
                                     d1_w, d2_w, W3_w);
    chain_mma<<<BSESS/16, 256, CH2_SMEM>>>(node_embedding, itemset_len,
                                           sequence,
                                           in_proj_b + 2*HD, out_proj_b,
                                           d1_b, d2_b, W3_b);
    cudaEventRecord(evChain, 0);

    // Side: yhat (needs chain) overlaps with scores.
    cudaStreamWaitEvent(sB, evChain, 0);
    yhat_kernel<<<BSESS, HD, 0, sB>>>(emb_weight, cue, out);
    cudaEventRecord(evSide, sB);

    // Main: scores (needs chain outputs + conv outputs).
    cudaStreamWaitEvent(0, evConv, 0);
    scores_kernel<<<dim3(8, (VOC + 127)/128), 256, SMEM_SZ>>>(out + BSESS);

    // Join side stream back into the capture-origin stream.
    cudaStreamWaitEvent(0, evSide, 0);
}